// round 4
// baseline (speedup 1.0000x reference)
#include <cuda_runtime.h>
#include <cuda_bf16.h>
#include <stdint.h>

// ======================= fragment-packed weight image =======================
#define OFF_B1    0
#define OFF_B0    28672
#define OFF_B1B   36864
#define OFF_BIAS1 40960
#define OFF_B0F   43008
#define OFF_B1F   44032
#define OFF_W2F   45056
#define OFF_B2    47104
#define PACK_BYTES 47120

__device__ __align__(16) unsigned char g_pack[PACK_BYTES];

// ======================= helpers =======================
__device__ __forceinline__ uint32_t pack_bf16x2(float a, float b) {
    __nv_bfloat16 ha = __float2bfloat16(a), hb = __float2bfloat16(b);
    return (uint32_t)__bfloat16_as_ushort(ha) | ((uint32_t)__bfloat16_as_ushort(hb) << 16);
}
__device__ __forceinline__ void bsplit(float f, float& h, float& l) {
    __nv_bfloat16 hb = __float2bfloat16(f);
    h = __bfloat162float(hb);
    l = f - h;
}
__device__ __forceinline__ void split_pack2(float f0, float f1, uint32_t& hr, uint32_t& lr) {
    float h0, l0, h1, l1;
    bsplit(f0, h0, l0);
    bsplit(f1, h1, l1);
    hr = pack_bf16x2(h0, h1);
    lr = pack_bf16x2(l0, l1);
}
__device__ __forceinline__ void mma16816(float* c, const uint32_t* a, uint32_t b0, uint32_t b1) {
    asm volatile(
        "mma.sync.aligned.m16n8k16.row.col.f32.bf16.bf16.f32 "
        "{%0,%1,%2,%3}, {%4,%5,%6,%7}, {%8,%9}, {%0,%1,%2,%3};"
        : "+f"(c[0]), "+f"(c[1]), "+f"(c[2]), "+f"(c[3])
        : "r"(a[0]), "r"(a[1]), "r"(a[2]), "r"(a[3]), "r"(b0), "r"(b1));
}

// ======================= prep kernel =======================
__device__ __forceinline__ float getW1c(const float* Ww, const float* Wb, int n, int k) {
    if (k >= 98) return 0.f;
    if (n < 32) return Ww[n * 98 + k];
    int kk = k + 49; if (kk >= 98) kk -= 98;
    return Wb[(n - 32) * 98 + kk];
}

__global__ void prep_kernel(const float* __restrict__ Ww, const float* __restrict__ Wb,
                            const float* __restrict__ W0, const float* __restrict__ W1,
                            const float* __restrict__ bw, const float* __restrict__ bb,
                            const float* __restrict__ b0, const float* __restrict__ b1,
                            const float* __restrict__ W2, const float* __restrict__ b2)
{
    const int tid = threadIdx.x;  // 256 threads
    char* gp = (char*)g_pack;

    for (int idx = tid; idx < 8 * 7 * 32; idx += 256) {
        int lane = idx & 31, t = idx >> 5;
        int kt = t % 7, nt = t / 7;
        int n = nt * 8 + (lane >> 2);
        int k0 = kt * 16 + (lane & 3) * 2;
        float w[4] = { getW1c(Ww, Wb, n, k0),     getW1c(Ww, Wb, n, k0 + 1),
                       getW1c(Ww, Wb, n, k0 + 8), getW1c(Ww, Wb, n, k0 + 9) };
        float h[4], l[4];
        for (int i = 0; i < 4; i++) bsplit(w[i], h[i], l[i]);
        uint4 v;
        v.x = pack_bf16x2(h[0], h[1]); v.y = pack_bf16x2(h[2], h[3]);
        v.z = pack_bf16x2(l[0], l[1]); v.w = pack_bf16x2(l[2], l[3]);
        ((uint4*)(gp + OFF_B1))[idx] = v;
    }
    for (int idx = tid; idx < 4 * 4 * 32; idx += 256) {
        int lane = idx & 31, t = idx >> 5;
        int kt = t & 3, nt = t >> 2;
        int n = nt * 8 + (lane >> 2);
        int k0 = kt * 16 + (lane & 3) * 2;
        float w[4] = { W0[n * 64 + k0],     W0[n * 64 + k0 + 1],
                       W0[n * 64 + k0 + 8], W0[n * 64 + k0 + 9] };
        float h[4], l[4];
        for (int i = 0; i < 4; i++) bsplit(w[i], h[i], l[i]);
        uint4 v;
        v.x = pack_bf16x2(h[0], h[1]); v.y = pack_bf16x2(h[2], h[3]);
        v.z = pack_bf16x2(l[0], l[1]); v.w = pack_bf16x2(l[2], l[3]);
        ((uint4*)(gp + OFF_B0))[idx] = v;
    }
    for (int idx = tid; idx < 4 * 2 * 32; idx += 256) {
        int lane = idx & 31, t = idx >> 5;
        int kt = t & 1, nt = t >> 1;
        int n = nt * 8 + (lane >> 2);
        int k0 = kt * 16 + (lane & 3) * 2;
        float w[4] = { W1[n * 32 + k0],     W1[n * 32 + k0 + 1],
                       W1[n * 32 + k0 + 8], W1[n * 32 + k0 + 9] };
        float h[4], l[4];
        for (int i = 0; i < 4; i++) bsplit(w[i], h[i], l[i]);
        uint4 v;
        v.x = pack_bf16x2(h[0], h[1]); v.y = pack_bf16x2(h[2], h[3]);
        v.z = pack_bf16x2(l[0], l[1]); v.w = pack_bf16x2(l[2], l[3]);
        ((uint4*)(gp + OFF_B1B))[idx] = v;
    }
    for (int idx = tid; idx < 4 * 32; idx += 256) {
        int lane = idx & 31, j = idx >> 5;
        int c = j * 8 + (lane & 3) * 2;
        float4 bf; bf.x = bw[c]; bf.y = bw[c + 1]; bf.z = bb[c]; bf.w = bb[c + 1];
        ((float4*)(gp + OFF_BIAS1))[idx] = bf;
        float2 f0; f0.x = b0[c]; f0.y = b0[c + 1];
        ((float2*)(gp + OFF_B0F))[idx] = f0;
        float2 f1; f1.x = b1[c]; f1.y = b1[c + 1];
        ((float2*)(gp + OFF_B1F))[idx] = f1;
        float4 w2; w2.x = W2[c]; w2.y = W2[c + 1]; w2.z = W2[32 + c]; w2.w = W2[32 + c + 1];
        ((float4*)(gp + OFF_W2F))[idx] = w2;
    }
    if (tid == 0) *((float*)(gp + OFF_B2)) = b2[0];
}

// ======================= main fused kernel =======================
// smem: st[128][100] staged inputs (cols 0-48 white, 49-97 black, 98-99 zero) + spov[128]
#define ST_STRIDE 100
#define SMEM_WORDS (128 * ST_STRIDE + 128)

__global__ void __launch_bounds__(128, 2)
nnue_main(const float* __restrict__ pov, const float* __restrict__ white,
          const float* __restrict__ black, float* __restrict__ out, int Btot)
{
    extern __shared__ float sh[];
    float* st   = sh;                    // [128][100]
    float* spov = sh + 128 * ST_STRIDE;  // [128]

    const int tid  = threadIdx.x;
    const int warp = tid >> 5;
    const int lane = tid & 31;
    const int q    = lane >> 2;
    const int qp   = lane & 3;
    const long long cbase = (long long)blockIdx.x * 128;

    // ---- stage inputs (coalesced, streaming) ----
    if (cbase + 128 <= (long long)Btot) {
        const float4* gw = (const float4*)(white + cbase * 49);
        const float4* gb = (const float4*)(black + cbase * 49);
        for (int i = tid; i < 1568; i += 128) {
            float4 v = __ldcs(gw + i);
            int g = 4 * i;
            #pragma unroll
            for (int e = 0; e < 4; e++) {
                int gg = g + e;
                int s = gg / 49, c = gg - s * 49;
                float val = (e == 0) ? v.x : (e == 1) ? v.y : (e == 2) ? v.z : v.w;
                st[s * ST_STRIDE + c] = val;
            }
            float4 u = __ldcs(gb + i);
            #pragma unroll
            for (int e = 0; e < 4; e++) {
                int gg = g + e;
                int s = gg / 49, c = gg - s * 49;
                float val = (e == 0) ? u.x : (e == 1) ? u.y : (e == 2) ? u.z : u.w;
                st[s * ST_STRIDE + 49 + c] = val;
            }
        }
        spov[tid] = __ldcs(pov + cbase + tid);
    } else {
        for (int i = tid; i < 6272; i += 128) {
            int s = i / 49, c = i - s * 49;
            long long row = cbase + s;
            bool ok = row < (long long)Btot;
            st[s * ST_STRIDE + c]      = ok ? white[row * 49 + c] : 0.f;
            st[s * ST_STRIDE + 49 + c] = ok ? black[row * 49 + c] : 0.f;
        }
        spov[tid] = (cbase + tid < (long long)Btot) ? pov[cbase + tid] : 0.f;
    }
    // zero pad cols 98,99
    st[tid * ST_STRIDE + 98] = 0.f;
    st[tid * ST_STRIDE + 99] = 0.f;
    __syncthreads();

    const int rbase = warp * 32;
    const int rw0  = (rbase + q) * ST_STRIDE;
    const int rw0b = rw0 + 8  * ST_STRIDE;
    const int rw1  = rw0 + 16 * ST_STRIDE;
    const int rw1b = rw0 + 24 * ST_STRIDE;

    const uint4*  B1u  = (const uint4*)(g_pack + OFF_B1);
    const uint4*  B0u  = (const uint4*)(g_pack + OFF_B0);
    const uint4*  B1bu = (const uint4*)(g_pack + OFF_B1B);
    const float4* bia1 = (const float4*)(g_pack + OFF_BIAS1);
    const float2* b0f  = (const float2*)(g_pack + OFF_B0F);
    const float2* b1f  = (const float2*)(g_pack + OFF_B1F);
    const float4* w2f  = (const float4*)(g_pack + OFF_W2F);

    // ================= layer 1 (both tiles share B) =================
    float cw[4][2][4], cbA[4][2][4];
    #pragma unroll
    for (int j = 0; j < 4; j++)
        #pragma unroll
        for (int t = 0; t < 2; t++)
            #pragma unroll
            for (int i = 0; i < 4; i++) { cw[j][t][i] = 0.f; cbA[j][t][i] = 0.f; }

    #pragma unroll
    for (int kt = 0; kt < 7; kt++) {
        uint32_t ah0[4], al0[4], ah1[4], al1[4];
        if (kt < 6) {
            int c0 = kt * 16 + qp * 2;
            float2 p;
            p = *(const float2*)(st + rw0  + c0);     split_pack2(p.x, p.y, ah0[0], al0[0]);
            p = *(const float2*)(st + rw0b + c0);     split_pack2(p.x, p.y, ah0[1], al0[1]);
            p = *(const float2*)(st + rw0  + c0 + 8); split_pack2(p.x, p.y, ah0[2], al0[2]);
            p = *(const float2*)(st + rw0b + c0 + 8); split_pack2(p.x, p.y, ah0[3], al0[3]);
            p = *(const float2*)(st + rw1  + c0);     split_pack2(p.x, p.y, ah1[0], al1[0]);
            p = *(const float2*)(st + rw1b + c0);     split_pack2(p.x, p.y, ah1[1], al1[1]);
            p = *(const float2*)(st + rw1  + c0 + 8); split_pack2(p.x, p.y, ah1[2], al1[2]);
            p = *(const float2*)(st + rw1b + c0 + 8); split_pack2(p.x, p.y, ah1[3], al1[3]);
        } else {
            #pragma unroll
            for (int i = 0; i < 4; i++) { ah0[i] = al0[i] = ah1[i] = al1[i] = 0u; }
            if (qp == 0) {
                float2 p;
                p = *(const float2*)(st + rw0  + 96); split_pack2(p.x, p.y, ah0[0], al0[0]);
                p = *(const float2*)(st + rw0b + 96); split_pack2(p.x, p.y, ah0[1], al0[1]);
                p = *(const float2*)(st + rw1  + 96); split_pack2(p.x, p.y, ah1[0], al1[0]);
                p = *(const float2*)(st + rw1b + 96); split_pack2(p.x, p.y, ah1[1], al1[1]);
            }
        }
        #pragma unroll
        for (int j = 0; j < 4; j++) {
            uint4 Bw = __ldg(B1u + (j * 7 + kt) * 32 + lane);
            uint4 Bb = __ldg(B1u + ((j + 4) * 7 + kt) * 32 + lane);
            mma16816(cw[j][0], ah0, Bw.x, Bw.y);
            mma16816(cw[j][0], al0, Bw.x, Bw.y);
            mma16816(cw[j][0], ah0, Bw.z, Bw.w);
            mma16816(cw[j][1], ah1, Bw.x, Bw.y);
            mma16816(cw[j][1], al1, Bw.x, Bw.y);
            mma16816(cw[j][1], ah1, Bw.z, Bw.w);
            mma16816(cbA[j][0], ah0, Bb.x, Bb.y);
            mma16816(cbA[j][0], al0, Bb.x, Bb.y);
            mma16816(cbA[j][0], ah0, Bb.z, Bb.w);
            mma16816(cbA[j][1], ah1, Bb.x, Bb.y);
            mma16816(cbA[j][1], al1, Bb.x, Bb.y);
            mma16816(cbA[j][1], ah1, Bb.z, Bb.w);
        }
    }

    // ---- epilogue 1: bias + pov mix + relu -> layer-0 A frags ----
    float pv0[2], pv1[2], pm0[2], pm1[2];
    #pragma unroll
    for (int t = 0; t < 2; t++) {
        pv0[t] = spov[rbase + t * 16 + q];
        pv1[t] = spov[rbase + t * 16 + q + 8];
        pm0[t] = 1.f - pv0[t];
        pm1[t] = 1.f - pv1[t];
    }
    uint32_t a0h[2][4][4], a0l[2][4][4];
    #pragma unroll
    for (int j = 0; j < 4; j++) {
        float4 bi = __ldg(bia1 + j * 32 + lane);
        #pragma unroll
        for (int t = 0; t < 2; t++) {
            float w0 = cw[j][t][0] + bi.x, w1 = cw[j][t][1] + bi.y;
            float w2_ = cw[j][t][2] + bi.x, w3 = cw[j][t][3] + bi.y;
            float bb0 = cbA[j][t][0] + bi.z, bb1 = cbA[j][t][1] + bi.w;
            float bb2 = cbA[j][t][2] + bi.z, bb3 = cbA[j][t][3] + bi.w;
            float vA0 = fmaxf(fmaf(pv0[t], w0, pm0[t] * bb0), 0.f);
            float vA1 = fmaxf(fmaf(pv0[t], w1, pm0[t] * bb1), 0.f);
            float vA2 = fmaxf(fmaf(pv1[t], w2_, pm1[t] * bb2), 0.f);
            float vA3 = fmaxf(fmaf(pv1[t], w3, pm1[t] * bb3), 0.f);
            float vB0 = fmaxf(fmaf(pv0[t], bb0, pm0[t] * w0), 0.f);
            float vB1 = fmaxf(fmaf(pv0[t], bb1, pm0[t] * w1), 0.f);
            float vB2 = fmaxf(fmaf(pv1[t], bb2, pm1[t] * w2_), 0.f);
            float vB3 = fmaxf(fmaf(pv1[t], bb3, pm1[t] * w3), 0.f);
            int ktw = j >> 1;
            int pos = (j & 1) ? 2 : 0;
            split_pack2(vA0, vA1, a0h[t][ktw][pos],     a0l[t][ktw][pos]);
            split_pack2(vA2, vA3, a0h[t][ktw][pos + 1], a0l[t][ktw][pos + 1]);
            split_pack2(vB0, vB1, a0h[t][ktw + 2][pos],     a0l[t][ktw + 2][pos]);
            split_pack2(vB2, vB3, a0h[t][ktw + 2][pos + 1], a0l[t][ktw + 2][pos + 1]);
        }
    }

    // ================= layer 0 =================
    float c0a[4][2][4];
    #pragma unroll
    for (int n = 0; n < 4; n++)
        #pragma unroll
        for (int t = 0; t < 2; t++)
            #pragma unroll
            for (int i = 0; i < 4; i++) c0a[n][t][i] = 0.f;
    #pragma unroll
    for (int kt = 0; kt < 4; kt++) {
        #pragma unroll
        for (int n = 0; n < 4; n++) {
            uint4 Bq = __ldg(B0u + (n * 4 + kt) * 32 + lane);
            #pragma unroll
            for (int t = 0; t < 2; t++) {
                mma16816(c0a[n][t], a0h[t][kt], Bq.x, Bq.y);
                mma16816(c0a[n][t], a0l[t][kt], Bq.x, Bq.y);
                mma16816(c0a[n][t], a0h[t][kt], Bq.z, Bq.w);
            }
        }
    }

    // ---- epilogue 0: x = relu(.+b0) ----
    float xv[2][4][4];
    uint32_t a1h[2][2][4], a1l[2][2][4];
    #pragma unroll
    for (int n = 0; n < 4; n++) {
        float2 bz = __ldg(b0f + n * 32 + lane);
        #pragma unroll
        for (int t = 0; t < 2; t++) {
            float x0 = fmaxf(c0a[n][t][0] + bz.x, 0.f);
            float x1 = fmaxf(c0a[n][t][1] + bz.y, 0.f);
            float x2 = fmaxf(c0a[n][t][2] + bz.x, 0.f);
            float x3 = fmaxf(c0a[n][t][3] + bz.y, 0.f);
            xv[t][n][0] = x0; xv[t][n][1] = x1; xv[t][n][2] = x2; xv[t][n][3] = x3;
            int ktw = n >> 1;
            int pos = (n & 1) ? 2 : 0;
            split_pack2(x0, x1, a1h[t][ktw][pos],     a1l[t][ktw][pos]);
            split_pack2(x2, x3, a1h[t][ktw][pos + 1], a1l[t][ktw][pos + 1]);
        }
    }

    // ================= layer 1b =================
    float c1a[4][2][4];
    #pragma unroll
    for (int n = 0; n < 4; n++)
        #pragma unroll
        for (int t = 0; t < 2; t++)
            #pragma unroll
            for (int i = 0; i < 4; i++) c1a[n][t][i] = 0.f;
    #pragma unroll
    for (int kt = 0; kt < 2; kt++) {
        #pragma unroll
        for (int n = 0; n < 4; n++) {
            uint4 Bq = __ldg(B1bu + (n * 2 + kt) * 32 + lane);
            #pragma unroll
            for (int t = 0; t < 2; t++) {
                mma16816(c1a[n][t], a1h[t][kt], Bq.x, Bq.y);
                mma16816(c1a[n][t], a1l[t][kt], Bq.x, Bq.y);
                mma16816(c1a[n][t], a1h[t][kt], Bq.z, Bq.w);
            }
        }
    }

    // ---- final: y = relu(.+b1); out = W2 . [x;y] + b2 ----
    float rA[2] = {0.f, 0.f}, rB[2] = {0.f, 0.f};
    #pragma unroll
    for (int n = 0; n < 4; n++) {
        float2 bz = __ldg(b1f + n * 32 + lane);
        float4 w2 = __ldg(w2f + n * 32 + lane);
        #pragma unroll
        for (int t = 0; t < 2; t++) {
            float y0 = fmaxf(c1a[n][t][0] + bz.x, 0.f);
            float y1 = fmaxf(c1a[n][t][1] + bz.y, 0.f);
            float y2 = fmaxf(c1a[n][t][2] + bz.x, 0.f);
            float y3 = fmaxf(c1a[n][t][3] + bz.y, 0.f);
            rA[t] = fmaf(w2.x, xv[t][n][0], rA[t]); rA[t] = fmaf(w2.y, xv[t][n][1], rA[t]);
            rA[t] = fmaf(w2.z, y0, rA[t]);          rA[t] = fmaf(w2.w, y1, rA[t]);
            rB[t] = fmaf(w2.x, xv[t][n][2], rB[t]); rB[t] = fmaf(w2.y, xv[t][n][3], rB[t]);
            rB[t] = fmaf(w2.z, y2, rB[t]);          rB[t] = fmaf(w2.w, y3, rB[t]);
        }
    }
    const float b2v = __ldg((const float*)(g_pack + OFF_B2));
    #pragma unroll
    for (int t = 0; t < 2; t++) {
        rA[t] += __shfl_xor_sync(0xFFFFFFFFu, rA[t], 1);
        rA[t] += __shfl_xor_sync(0xFFFFFFFFu, rA[t], 2);
        rB[t] += __shfl_xor_sync(0xFFFFFFFFu, rB[t], 1);
        rB[t] += __shfl_xor_sync(0xFFFFFFFFu, rB[t], 2);
    }
    if (qp == 0) {
        #pragma unroll
        for (int t = 0; t < 2; t++) {
            long long rowA = cbase + rbase + t * 16 + q;
            long long rowB = rowA + 8;
            if (rowA < (long long)Btot) out[rowA] = rA[t] + b2v;
            if (rowB < (long long)Btot) out[rowB] = rB[t] + b2v;
        }
    }
}

// ======================= launch =======================
extern "C" void kernel_launch(void* const* d_in, const int* in_sizes, int n_in,
                              void* d_out, int out_size) {
    const float* pov   = (const float*)d_in[0];
    const float* white = (const float*)d_in[1];
    const float* black = (const float*)d_in[2];
    const float* Ww = (const float*)d_in[3];
    const float* bw = (const float*)d_in[4];
    const float* Wb = (const float*)d_in[5];
    const float* bb = (const float*)d_in[6];
    const float* W0 = (const float*)d_in[7];
    const float* b0 = (const float*)d_in[8];
    const float* W1 = (const float*)d_in[9];
    const float* b1 = (const float*)d_in[10];
    const float* W2 = (const float*)d_in[11];
    const float* b2 = (const float*)d_in[12];
    const int B = in_sizes[0];

    prep_kernel<<<1, 256>>>(Ww, Wb, W0, W1, bw, bb, b0, b1, W2, b2);

    const int smem_bytes = SMEM_WORDS * 4;  // 51712 B
    cudaFuncSetAttribute(nnue_main, cudaFuncAttributeMaxDynamicSharedMemorySize, smem_bytes);
    int grid = (B + 127) >> 7;
    nnue_main<<<grid, 128, smem_bytes>>>(pov, white, black, (float*)d_out, B);
}